// round 17
// baseline (speedup 1.0000x reference)
#include <cuda_runtime.h>
#include <cuda_fp16.h>
#include <cstdint>

#define BB 32
#define LL 512
#define DD 1024
#define RR 128
#define M_TOTAL (BB * LL)   // 16384

// ---------------- global scratch ----------------
__device__ __align__(16) __half g_pT[RR * DD];        // projT [128][1024] fp16 (rn)
__device__ __align__(16) __half g_th[M_TOTAL * RR];   // T-hat [16384][128] fp16
__device__ float g_sqn[M_TOTAL];                      // norms of T-hat (fp32)

__constant__ int c_ti[10] = {0,0,0,0,1,1,1,2,2,3};
__constant__ int c_tj[10] = {0,1,2,3,1,2,3,2,3,3};

// ---------------- helpers (arch-feature-free PTX only) ----------------
__device__ __forceinline__ uint32_t smem_u32(const void* p) {
    uint32_t a;
    asm("{ .reg .u64 t; cvta.to.shared.u64 t, %1; cvt.u32.u64 %0, t; }" : "=r"(a) : "l"(p));
    return a;
}
__device__ __forceinline__ void ldsm4(uint32_t r[4], uint32_t addr) {
    asm volatile("ldmatrix.sync.aligned.m8n8.x4.shared.b16 {%0,%1,%2,%3}, [%4];"
                 : "=r"(r[0]), "=r"(r[1]), "=r"(r[2]), "=r"(r[3]) : "r"(addr));
}
__device__ __forceinline__ void mma_f16(float d[4], const uint32_t a[4],
                                        uint32_t b0, uint32_t b1) {
    asm volatile(
        "mma.sync.aligned.m16n8k16.row.col.f32.f16.f16.f32 "
        "{%0,%1,%2,%3},{%4,%5,%6,%7},{%8,%9},{%0,%1,%2,%3};"
        : "+f"(d[0]), "+f"(d[1]), "+f"(d[2]), "+f"(d[3])
        : "r"(a[0]), "r"(a[1]), "r"(a[2]), "r"(a[3]), "r"(b0), "r"(b1));
}
#define CP16(dst, src) \
    asm volatile("cp.async.cg.shared.global [%0], [%1], 16;" :: "r"(dst), "l"(src) : "memory")
#define CP_COMMIT() asm volatile("cp.async.commit_group;" ::: "memory")
#define CP_WAIT(n)  asm volatile("cp.async.wait_group %0;" :: "n"(n) : "memory")

__device__ __forceinline__ uint32_t pack_f16x2(float a, float b) {
    __half2 h = __floats2half2_rn(a, b);
    return *reinterpret_cast<uint32_t*>(&h);
}
__device__ __forceinline__ float2 unpack_f16x2(uint32_t u) {
    __half2 h = *reinterpret_cast<__half2*>(&u);
    return __half22float2(h);
}

// ---------------------------------------------------------------------------
// Kernel 0: transpose proj (D,R) fp32 -> projT (R,D) fp16 (rn).
// ---------------------------------------------------------------------------
__global__ __launch_bounds__(256) void prep_proj_kernel(const float* __restrict__ proj) {
    __shared__ float sT[32][33];
    const int tid = threadIdx.x;
    const int k0 = blockIdx.x * 32;
    const int r0 = blockIdx.y * 32;

#pragma unroll
    for (int t = 0; t < 2; ++t) {
        const int idx = tid + t * 256;
        const int k = idx >> 4, c2 = idx & 15;
        float2 v = *reinterpret_cast<const float2*>(proj + (size_t)(k0 + k) * RR + r0 + c2 * 2);
        sT[k][c2 * 2] = v.x;
        sT[k][c2 * 2 + 1] = v.y;
    }
    __syncthreads();

    {
        const int r = tid >> 3, kq = tid & 7;
        float f[4];
#pragma unroll
        for (int e = 0; e < 4; ++e) f[e] = sT[kq * 4 + e][r];
        uint2 hv;
        hv.x = pack_f16x2(f[0], f[1]);
        hv.y = pack_f16x2(f[2], f[3]);
        const size_t o = (size_t)(r0 + r) * DD + k0 + kq * 4;
        *reinterpret_cast<uint2*>(g_pT + o) = hv;
    }
}

// ---------------------------------------------------------------------------
// Kernel 1: T = batch @ proj (16384x128, K=1024), SINGLE-term fp16:
//   T ~= fp16(A) * fp16(B), fp32 accum.
// CTA 128x128, grid 128, 256 thr, warp tile 32x64, BK=64 (16 iters).
// XOR-swizzled 128B rows, double-buffered 2x32KB.
// Epilogue: t-hat = fp16(acc); store; norms from ROUNDED t-hat so that
// gemm2's single-term product gives distance = |t̂i - t̂j|^2 exactly.
// ---------------------------------------------------------------------------
#define A1_ARR 16384                  // 128 rows x 128B
#define B1_ARR 16384
#define G1_BUF (A1_ARR + B1_ARR)      // 32768
#define G1_SMEM (2 * G1_BUF)          // 65536

__global__ __launch_bounds__(256) void gemm1_kernel(const float* __restrict__ batch) {
    extern __shared__ __align__(16) char sm1[];
    __shared__ float sSq[128][2];
    const uint32_t base = smem_u32(sm1);

    const int tid = threadIdx.x;
    const int wid = tid >> 5;
    const int lane = tid & 31;
    const int row0 = blockIdx.x * 128;
    const int wm = (wid & 3) * 32;      // M group within 128
    const int wn = (wid >> 2) * 64;     // N half within 128

    // loader maps
    const int a_row = tid >> 4, a_k4 = tid & 15;  // A: 128 rows x 16 float4, 8 per thread
    const int b_row = tid >> 3, b_c = tid & 7;    // B: 128 rows x 8 16B chunks

    const uint32_t a_sts = (uint32_t)(a_row * 128 + (((a_k4 >> 1) ^ (a_row & 7)) << 4) + (a_k4 & 1) * 8);
    const uint32_t b_cp  = (uint32_t)(b_row * 128 + ((b_c ^ (b_row & 7)) << 4));

    // ldmatrix lane pieces
    const int lx = lane & 7;
    const int a_bit = (lane >> 4) & 1;
    const int b_bit = (lane >> 3) & 1;
    const uint32_t a_rb0 = (uint32_t)((wm + (lane & 15)) * 128);
    const uint32_t a_rb1 = a_rb0 + 16 * 128;
    const int b_lrow = (lane & 7) + ((lane >> 4) & 1) * 8;

    float acc[2][8][4];
#pragma unroll
    for (int mi = 0; mi < 2; mi++)
#pragma unroll
        for (int g = 0; g < 8; g++)
#pragma unroll
            for (int j = 0; j < 4; j++) acc[mi][g][j] = 0.0f;

    float4 pfa[8];

    // ---- prologue: iter 0 ----
#pragma unroll
    for (int t = 0; t < 8; ++t) {
        const int row = a_row + t * 16;
        pfa[t] = *reinterpret_cast<const float4*>(
            batch + (size_t)(row0 + row) * DD + a_k4 * 4);
    }
    {
        const uint32_t bb = base;
#pragma unroll
        for (int t = 0; t < 4; ++t) {
            const int row = b_row + t * 32;
            const uint32_t off = b_cp + (uint32_t)(t * 32 * 128);
            CP16(bb + A1_ARR + off, g_pT + (size_t)row * DD + b_c * 8);
        }
        CP_COMMIT();
#pragma unroll
        for (int t = 0; t < 8; ++t) {
            float4 v = pfa[t];
            uint32_t h01 = pack_f16x2(v.x, v.y);
            uint32_t h23 = pack_f16x2(v.z, v.w);
            asm volatile("st.shared.v2.b32 [%0], {%1,%2};"
                :: "r"(bb + a_sts + (uint32_t)(t * 16 * 128)), "r"(h01), "r"(h23) : "memory");
        }
    }
    CP_WAIT(0);
    __syncthreads();

    for (int it = 0; it < 16; ++it) {
        const int p = it & 1;
        const uint32_t bb = base + p * G1_BUF;
        const uint32_t nb = base + (p ^ 1) * G1_BUF;

        if (it < 15) {
            const int k0n = (it + 1) * 64;
#pragma unroll
            for (int t = 0; t < 4; ++t) {
                const int row = b_row + t * 32;
                const uint32_t off = b_cp + (uint32_t)(t * 32 * 128);
                CP16(nb + A1_ARR + off, g_pT + (size_t)row * DD + k0n + b_c * 8);
            }
            CP_COMMIT();
#pragma unroll
            for (int t = 0; t < 8; ++t) {
                const int row = a_row + t * 16;
                pfa[t] = *reinterpret_cast<const float4*>(
                    batch + (size_t)(row0 + row) * DD + k0n + a_k4 * 4);
            }
        }

        // compute on buffer p: 4 k16 steps, warp tile 32x64, single term
#pragma unroll
        for (int s = 0; s < 4; ++s) {
            const uint32_t asw = (uint32_t)((((2 * s + a_bit) ^ lx) << 4));
            const uint32_t bsw = (uint32_t)((((2 * s + b_bit) ^ lx) << 4));
            uint32_t Ah[2][4];
            ldsm4(Ah[0], bb + a_rb0 + asw);
            ldsm4(Ah[1], bb + a_rb1 + asw);
#pragma unroll
            for (int ng = 0; ng < 4; ++ng) {
                const uint32_t brb = (uint32_t)((wn + ng * 16 + b_lrow) * 128);
                uint32_t Bh4[4];
                ldsm4(Bh4, bb + A1_ARR + brb + bsw);
#pragma unroll
                for (int mi = 0; mi < 2; ++mi) {
                    mma_f16(acc[mi][ng * 2 + 0], Ah[mi], Bh4[0], Bh4[1]);
                    mma_f16(acc[mi][ng * 2 + 1], Ah[mi], Bh4[2], Bh4[3]);
                }
            }
        }

        if (it < 15) {
#pragma unroll
            for (int t = 0; t < 8; ++t) {
                float4 v = pfa[t];
                uint32_t h01 = pack_f16x2(v.x, v.y);
                uint32_t h23 = pack_f16x2(v.z, v.w);
                asm volatile("st.shared.v2.b32 [%0], {%1,%2};"
                    :: "r"(nb + a_sts + (uint32_t)(t * 16 * 128)), "r"(h01), "r"(h23) : "memory");
            }
            CP_WAIT(0);
        }
        __syncthreads();
    }

    // Epilogue: t-hat = fp16(acc), store; norms accumulated from ROUNDED vals.
    uint32_t* th32 = reinterpret_cast<uint32_t*>(g_th);
#pragma unroll
    for (int mi = 0; mi < 2; ++mi) {
        const int lr = wm + mi * 16 + (lane >> 2);
        const int g0 = row0 + lr, g1 = g0 + 8;
        float sq0 = 0.0f, sq1 = 0.0f;
#pragma unroll
        for (int g = 0; g < 8; ++g) {
            uint32_t h01 = pack_f16x2(acc[mi][g][0], acc[mi][g][1]);
            uint32_t h23 = pack_f16x2(acc[mi][g][2], acc[mi][g][3]);
            float2 r01 = unpack_f16x2(h01);
            float2 r23 = unpack_f16x2(h23);
            sq0 = fmaf(r01.x, r01.x, sq0); sq0 = fmaf(r01.y, r01.y, sq0);
            sq1 = fmaf(r23.x, r23.x, sq1); sq1 = fmaf(r23.y, r23.y, sq1);
            const int cidx = wn / 2 + g * 4 + (lane & 3);
            th32[(size_t)g0 * 64 + cidx] = h01;
            th32[(size_t)g1 * 64 + cidx] = h23;
        }
#pragma unroll
        for (int o = 1; o <= 2; o <<= 1) {
            sq0 += __shfl_xor_sync(0xffffffffu, sq0, o);
            sq1 += __shfl_xor_sync(0xffffffffu, sq1, o);
        }
        if ((lane & 3) == 0) {
            sSq[lr][wid >> 2] = sq0;
            sSq[lr + 8][wid >> 2] = sq1;
        }
    }
    __syncthreads();
    if (tid < 128) g_sqn[row0 + tid] = sSq[tid][0] + sSq[tid][1];
}

// ---------------------------------------------------------------------------
// Kernel 2: symmetric Gram tiles, SINGLE-term fp16: c = t̂i · t̂j.
// Grid (10, 32), 256 thr, warp tile 32x64, 2 smem tiles (A, B) -> 3 CTAs/SM
// => 320 CTAs in ONE wave. Mirror via conflict-free smem transpose.
// ---------------------------------------------------------------------------
#define S2B 272                        // bytes per smem row (136 fp16)
#define G2_TILE (128 * S2B)            // 34816
#define G2_SMEM (2 * G2_TILE + 1024)   // 70656

__global__ __launch_bounds__(256, 3) void gemm2_kernel(float* __restrict__ out) {
    extern __shared__ __align__(16) char sm2[];
    const uint32_t ah = smem_u32(sm2);
    const uint32_t bh = ah + G2_TILE;
    float* sNi = reinterpret_cast<float*>(sm2 + 2 * G2_TILE);
    float* sNj = sNi + 128;
    float* sD  = reinterpret_cast<float*>(sm2);   // transpose staging (aliases tiles)

    const int tid = threadIdx.x;
    const int wid = tid >> 5;
    const int lane = tid & 31;
    const int b = blockIdx.y;
    const int ti = c_ti[blockIdx.x], tj = c_tj[blockIdx.x];
    const bool diag = (ti == tj);
    const int i0 = ti * 128, j0 = tj * 128;
    const int wm = (wid & 3) * 32;
    const int wn = (wid >> 2) * 64;

    const __half* srcs[2] = {
        g_th + (size_t)(b * LL + i0) * RR,   // -> ah
        g_th + (size_t)(b * LL + j0) * RR }; // -> bh (off-diag only)
    const uint32_t dsts[2] = { ah, bh };
    const int ntile = diag ? 1 : 2;

    // Split-K cp.async: group 0 = k[0,64), group 1 = k[64,128)
#pragma unroll
    for (int h = 0; h < 2; ++h) {
        for (int r = 0; r < ntile; ++r) {
#pragma unroll
            for (int q = 0; q < 4; ++q) {
                const int idx = tid + q * 256;
                const int row = idx >> 3, kcl = idx & 7;
                const int kc = h * 8 + kcl;
                CP16(dsts[r] + (uint32_t)(row * S2B + kc * 16),
                     srcs[r] + (size_t)row * RR + kc * 8);
            }
        }
        CP_COMMIT();
    }
    if (tid < 128) sNi[tid] = g_sqn[b * LL + i0 + tid];
    else sNj[tid - 128] = g_sqn[b * LL + j0 + (tid - 128)];

    const uint32_t bhc = diag ? ah : bh;
    const uint32_t a_off0 = (uint32_t)((wm + (lane & 15)) * S2B + ((lane >> 4) & 1) * 16);
    const uint32_t a_off1 = a_off0 + (uint32_t)(16 * S2B);
    const uint32_t b_base = (uint32_t)(((lane & 7) + ((lane >> 4) & 1) * 8) * S2B + ((lane >> 3) & 1) * 16);

    float acc[2][8][4];
#pragma unroll
    for (int mi = 0; mi < 2; mi++)
#pragma unroll
        for (int g = 0; g < 8; g++)
#pragma unroll
            for (int j = 0; j < 4; j++) acc[mi][g][j] = 0.0f;

    CP_WAIT(1);
    __syncthreads();

#pragma unroll
    for (int s = 0; s < 8; ++s) {
        if (s == 4) { CP_WAIT(0); __syncthreads(); }
        uint32_t Ah[2][4];
        ldsm4(Ah[0], ah + a_off0 + s * 32);
        ldsm4(Ah[1], ah + a_off1 + s * 32);
#pragma unroll
        for (int ng = 0; ng < 4; ++ng) {
            const uint32_t brb = b_base + (uint32_t)((wn + ng * 16) * S2B) + s * 32;
            uint32_t Bh4[4];
            ldsm4(Bh4, bhc + brb);
#pragma unroll
            for (int mi = 0; mi < 2; ++mi) {
                mma_f16(acc[mi][ng * 2 + 0], Ah[mi], Bh4[0], Bh4[1]);
                mma_f16(acc[mi][ng * 2 + 1], Ah[mi], Bh4[2], Bh4[3]);
            }
        }
    }
    __syncthreads();   // all ldsm done before sD overwrites tile smem

    // Epilogue: d = max(ni + nj - 2c, 0); direct block + staged mirror.
#pragma unroll
    for (int mi = 0; mi < 2; ++mi) {
        const int r = wm + mi * 16 + (lane >> 2);
        const float ni0 = sNi[r], ni1 = sNi[r + 8];
        float* o0 = out + ((size_t)(b * LL + i0 + r)) * LL + j0;
        float* o1 = o0 + 8 * LL;
#pragma unroll
        for (int g = 0; g < 8; ++g) {
            const int col = wn + g * 8 + (lane & 3) * 2;
            const float nj0 = sNj[col], nj1 = sNj[col + 1];
            float2 v0, v1;
            v0.x = fmaxf(ni0 + nj0 - 2.0f * acc[mi][g][0], 0.0f);
            v0.y = fmaxf(ni0 + nj1 - 2.0f * acc[mi][g][1], 0.0f);
            v1.x = fmaxf(ni1 + nj0 - 2.0f * acc[mi][g][2], 0.0f);
            v1.y = fmaxf(ni1 + nj1 - 2.0f * acc[mi][g][3], 0.0f);
            *reinterpret_cast<float2*>(o0 + col) = v0;
            *reinterpret_cast<float2*>(o1 + col) = v1;
            if (!diag) {
                sD[col * 132 + r]           = v0.x;   // sD_T[c][r]
                sD[(col + 1) * 132 + r]     = v0.y;
                sD[col * 132 + r + 8]       = v1.x;
                sD[(col + 1) * 132 + r + 8] = v1.y;
            }
        }
    }
    if (!diag) {
        __syncthreads();
#pragma unroll
        for (int t = 0; t < 16; ++t) {
            const int idx = tid + t * 256;
            const int tr = idx >> 5;                 // transposed row = orig col
            float4 v = *reinterpret_cast<const float4*>(sD + (size_t)tr * 132 + lane * 4);
            *reinterpret_cast<float4*>(
                out + ((size_t)(b * LL + j0 + tr)) * LL + i0 + lane * 4) = v;
        }
    }
}

extern "C" void kernel_launch(void* const* d_in, const int* in_sizes, int n_in,
                              void* d_out, int out_size)
{
    const float* batch = (const float*)d_in[0];  // (32, 512, 1024) f32
    const float* proj  = (const float*)d_in[1];  // (1024, 128) f32
    float* out = (float*)d_out;                  // (32, 512, 512) f32

    cudaFuncSetAttribute(gemm1_kernel, cudaFuncAttributeMaxDynamicSharedMemorySize, G1_SMEM);
    cudaFuncSetAttribute(gemm2_kernel, cudaFuncAttributeMaxDynamicSharedMemorySize, G2_SMEM);

    prep_proj_kernel<<<dim3(32, 4), 256>>>(proj);
    gemm1_kernel<<<M_TOTAL / 128, 256, G1_SMEM>>>(batch);
    gemm2_kernel<<<dim3(10, BB), 256, G2_SMEM>>>(out);
}